// round 2
// baseline (speedup 1.0000x reference)
#include <cuda_runtime.h>

// Problem constants: pred_softmax (16, 11, 1, 512, 512) fp32; use parts 0..9.
#define B_DIM   16
#define P_FULL  11
#define P_USE   10
#define HW      512
#define NIMG    (B_DIM * P_USE)          // 160
#define BLOCKS_PER_IMG 16
#define NPART   (NIMG * BLOCKS_PER_IMG)  // 2560
#define THREADS 256

// Per-block partial sums: [S, Sx, Sxx, Sy, Syy]. Written fully every launch
// (deterministic, no atomics, no zeroing needed).
__device__ float g_part[NPART][5];

__global__ __launch_bounds__(THREADS) void moments_kernel(const float* __restrict__ in) {
    const int img = blockIdx.x / BLOCKS_PER_IMG;   // 0..159
    const int sub = blockIdx.x % BLOCKS_PER_IMG;   // 0..15
    const int b = img / P_USE;
    const int p = img % P_USE;

    const float4* __restrict__ base =
        (const float4*)(in + ((size_t)b * P_FULL + p) * (size_t)HW * HW);

    const float inv = 2.0f / (float)HW;   // 0.00390625, exact in fp32
    const int tid = threadIdx.x;

    float S = 0.f, Sx = 0.f, Sxx = 0.f, Sy = 0.f, Syy = 0.f;

    // Each block: 32 rows x 128 float4 = 4096 quads; 256 threads x 16 iters.
    #pragma unroll
    for (int i = 0; i < 16; ++i) {
        int q  = tid + THREADS * i;            // 0..4095
        int r  = sub * 32 + (q >> 7);          // global row 0..511
        int cq = q & 127;                      // quad index within row
        float4 v = __ldg(&base[(size_t)r * 128 + cq]);

        float ym = (float)r * inv - 1.0f;
        float x0 = (float)(cq * 4) * inv - 1.0f;
        float x1 = x0 + inv;
        float x2 = x0 + 2.0f * inv;
        float x3 = x0 + 3.0f * inv;

        float rs = (v.x + v.y) + (v.z + v.w);
        S  += rs;
        Sy  = fmaf(rs, ym, Sy);
        Syy = fmaf(rs * ym, ym, Syy);

        float sx = fmaf(v.x, x0, fmaf(v.y, x1, fmaf(v.z, x2, v.w * x3)));
        Sx += sx;
        Sxx = fmaf(v.x * x0, x0, fmaf(v.y * x1, x1,
              fmaf(v.z * x2, x2, fmaf(v.w * x3, x3, Sxx))));
    }

    // Warp reduction of the 5 sums.
    #pragma unroll
    for (int off = 16; off > 0; off >>= 1) {
        S   += __shfl_xor_sync(0xFFFFFFFFu, S,   off);
        Sx  += __shfl_xor_sync(0xFFFFFFFFu, Sx,  off);
        Sxx += __shfl_xor_sync(0xFFFFFFFFu, Sxx, off);
        Sy  += __shfl_xor_sync(0xFFFFFFFFu, Sy,  off);
        Syy += __shfl_xor_sync(0xFFFFFFFFu, Syy, off);
    }

    __shared__ float sh[8][5];
    int wid = tid >> 5, lid = tid & 31;
    if (lid == 0) {
        sh[wid][0] = S; sh[wid][1] = Sx; sh[wid][2] = Sxx;
        sh[wid][3] = Sy; sh[wid][4] = Syy;
    }
    __syncthreads();

    if (wid == 0 && lid < 5) {
        float acc = 0.f;
        #pragma unroll
        for (int w = 0; w < 8; ++w) acc += sh[w][lid];
        g_part[blockIdx.x][lid] = acc;
    }
}

__global__ __launch_bounds__(THREADS) void finalize_kernel(float* __restrict__ out) {
    __shared__ float sh[THREADS];
    const int t = threadIdx.x;
    float contrib = 0.f;

    if (t < NIMG) {
        float S = 0.f, Sx = 0.f, Sxx = 0.f, Sy = 0.f, Syy = 0.f;
        #pragma unroll
        for (int s = 0; s < BLOCKS_PER_IMG; ++s) {
            const float* pp = g_part[t * BLOCKS_PER_IMG + s];
            S += pp[0]; Sx += pp[1]; Sxx += pp[2]; Sy += pp[3]; Syy += pp[4];
        }
        float k    = S + 1e-8f;
        float invk = 1.0f / k;
        float xc   = Sx * invk;
        float yc   = Sy * invk;
        float spdf = S * invk;   // sum of pdf (≈1)
        // v = Σ pdf (m - c)^2 = M2/k - 2 c^2 + c^2 * spdf
        float vx = Sxx * invk - 2.0f * xc * xc + xc * xc * spdf;
        float vy = Syy * invk - 2.0f * yc * yc + yc * yc * spdf;
        contrib = vx + vy;
    }
    sh[t] = contrib;
    __syncthreads();
    #pragma unroll
    for (int off = THREADS / 2; off > 0; off >>= 1) {
        if (t < off) sh[t] += sh[t + off];
        __syncthreads();
    }
    if (t == 0) out[0] = sh[0] / (float)B_DIM;
}

extern "C" void kernel_launch(void* const* d_in, const int* in_sizes, int n_in,
                              void* d_out, int out_size) {
    const float* in = (const float*)d_in[0];
    float* out = (float*)d_out;
    moments_kernel<<<NPART, THREADS>>>(in);
    finalize_kernel<<<1, THREADS>>>(out);
}

// round 5
// speedup vs baseline: 1.0576x; 1.0576x over previous
#include <cuda_runtime.h>

// Problem constants: pred_softmax (16, 11, 1, 512, 512) fp32; use parts 0..9.
#define B_DIM   16
#define P_FULL  11
#define P_USE   10
#define HW      512
#define NIMG    (B_DIM * P_USE)          // 160
#define BLOCKS_PER_IMG 16
#define NPART   (NIMG * BLOCKS_PER_IMG)  // 2560
#define THREADS 256

// SoA partial sums: component-major so the finalizing block reads each image's
// 16 partials as 4 contiguous float4 loads. Written fully every launch.
__device__ float g_part[5][NPART];
__device__ unsigned int g_ticket;   // zero-init; atomicInc wraps back to 0

__global__ __launch_bounds__(THREADS) void fused_kernel(const float* __restrict__ in,
                                                        float* __restrict__ out) {
    const int bid = blockIdx.x;
    const int img = bid / BLOCKS_PER_IMG;   // 0..159
    const int sub = bid % BLOCKS_PER_IMG;   // 0..15
    const int b = img / P_USE;
    const int p = img % P_USE;

    const float4* __restrict__ base =
        (const float4*)(in + ((size_t)b * P_FULL + p) * (size_t)HW * HW);

    const float inv = 2.0f / (float)HW;   // exact in fp32
    const int tid = threadIdx.x;

    float S = 0.f, Sx = 0.f, Sxx = 0.f, Sy = 0.f, Syy = 0.f;

    // Each block: 32 rows x 128 float4 = 4096 quads; 256 threads x 16 iters.
    #pragma unroll
    for (int i = 0; i < 16; ++i) {
        int q  = tid + THREADS * i;            // 0..4095
        int r  = sub * 32 + (q >> 7);          // global row 0..511
        int cq = q & 127;                      // quad index within row
        float4 v = __ldg(&base[(size_t)r * 128 + cq]);

        float ym = (float)r * inv - 1.0f;
        float x0 = (float)(cq * 4) * inv - 1.0f;
        float x1 = x0 + inv;
        float x2 = x0 + 2.0f * inv;
        float x3 = x0 + 3.0f * inv;

        float rs = (v.x + v.y) + (v.z + v.w);
        S  += rs;
        Sy  = fmaf(rs, ym, Sy);
        Syy = fmaf(rs * ym, ym, Syy);

        float sx = fmaf(v.x, x0, fmaf(v.y, x1, fmaf(v.z, x2, v.w * x3)));
        Sx += sx;
        Sxx = fmaf(v.x * x0, x0, fmaf(v.y * x1, x1,
              fmaf(v.z * x2, x2, fmaf(v.w * x3, x3, Sxx))));
    }

    // Warp reduction of the 5 sums.
    #pragma unroll
    for (int off = 16; off > 0; off >>= 1) {
        S   += __shfl_xor_sync(0xFFFFFFFFu, S,   off);
        Sx  += __shfl_xor_sync(0xFFFFFFFFu, Sx,  off);
        Sxx += __shfl_xor_sync(0xFFFFFFFFu, Sxx, off);
        Sy  += __shfl_xor_sync(0xFFFFFFFFu, Sy,  off);
        Syy += __shfl_xor_sync(0xFFFFFFFFu, Syy, off);
    }

    __shared__ float sh[8][5];
    __shared__ bool  isLast;
    const int wid = tid >> 5, lid = tid & 31;
    if (lid == 0) {
        sh[wid][0] = S; sh[wid][1] = Sx; sh[wid][2] = Sxx;
        sh[wid][3] = Sy; sh[wid][4] = Syy;
    }
    __syncthreads();

    // Single-writer store of the 5 block partials (airtight release ordering:
    // store -> threadfence -> atomic ticket).
    if (tid == 0) {
        #pragma unroll
        for (int c = 0; c < 5; ++c) {
            float acc = 0.f;
            #pragma unroll
            for (int w = 0; w < 8; ++w) acc += sh[w][c];
            g_part[c][bid] = acc;
        }
        __threadfence();
        unsigned int t = atomicInc(&g_ticket, NPART - 1);  // wraps to 0 on last
        isLast = (t == NPART - 1);
    }
    __syncthreads();

    if (!isLast) return;

    // ---- Last block finalizes (partials are L2-hot) ----
    __shared__ float red[THREADS];
    float contrib = 0.f;
    if (tid < NIMG) {
        float s[5];
        #pragma unroll
        for (int c = 0; c < 5; ++c) {
            const float4* p4 = (const float4*)&g_part[c][tid * BLOCKS_PER_IMG];
            float4 a = p4[0], bq = p4[1], cc = p4[2], d = p4[3];
            s[c] = ((a.x + a.y) + (a.z + a.w)) + ((bq.x + bq.y) + (bq.z + bq.w))
                 + ((cc.x + cc.y) + (cc.z + cc.w)) + ((d.x + d.y) + (d.z + d.w));
        }
        float k    = s[0] + 1e-8f;
        float invk = 1.0f / k;
        float xc   = s[1] * invk;
        float yc   = s[3] * invk;
        float spdf = s[0] * invk;   // Σ pdf (≈1)
        // v = Σ pdf (m - c)^2 = M2/k - 2 c^2 + c^2 * Σpdf
        float vx = s[2] * invk - 2.0f * xc * xc + xc * xc * spdf;
        float vy = s[4] * invk - 2.0f * yc * yc + yc * yc * spdf;
        contrib = vx + vy;
    }
    red[tid] = contrib;
    __syncthreads();
    #pragma unroll
    for (int off = THREADS / 2; off > 0; off >>= 1) {
        if (tid < off) red[tid] += red[tid + off];
        __syncthreads();
    }
    if (tid == 0) out[0] = red[0] / (float)B_DIM;
}

extern "C" void kernel_launch(void* const* d_in, const int* in_sizes, int n_in,
                              void* d_out, int out_size) {
    const float* in = (const float*)d_in[0];
    float* out = (float*)d_out;
    fused_kernel<<<NPART, THREADS>>>(in, out);
}

// round 7
// speedup vs baseline: 1.1308x; 1.0692x over previous
#include <cuda_runtime.h>

// Problem constants: pred_softmax (16, 11, 1, 512, 512) fp32; use parts 0..9.
#define B_DIM   16
#define P_FULL  11
#define P_USE   10
#define HW      512
#define NIMG    (B_DIM * P_USE)          // 160
#define BLOCKS_PER_IMG 8
#define NPART   (NIMG * BLOCKS_PER_IMG)  // 1280
#define THREADS 256
#define QPT     32                       // float4 quads per thread
#define BATCH   8                        // loads in flight per thread

// SoA partial sums: component-major so the finalizing block reads each image's
// 8 partials as 2 contiguous float4 loads. Written fully every launch.
__device__ __align__(16) float g_part[5][NPART];
__device__ unsigned int g_ticket;   // zero-init; atomicInc wraps back to 0

__global__ __launch_bounds__(THREADS) void fused_kernel(const float* __restrict__ in,
                                                        float* __restrict__ out) {
    const int bid = blockIdx.x;
    const int img = bid / BLOCKS_PER_IMG;   // 0..159
    const int sub = bid % BLOCKS_PER_IMG;   // 0..7  (64-row slab)
    const int b = img / P_USE;
    const int p = img % P_USE;

    const int tid = threadIdx.x;
    const float inv = 2.0f / (float)HW;     // exact in fp32
    const float dy  = 2.0f * inv;           // row step per iteration

    // Block slab is contiguous: 64 rows x 128 quads = 8192 quads.
    const float4* __restrict__ pbase =
        (const float4*)(in + ((size_t)b * P_FULL + p) * (size_t)HW * HW)
        + (size_t)sub * 8192 + tid;

    // Column (x) coordinates are invariant per thread: cq = tid & 127.
    const float x0 = (float)(4 * (tid & 127)) * inv - 1.0f;
    const float x1 = x0 + inv;
    const float x2 = x0 + 2.0f * inv;
    const float x3 = x0 + 3.0f * inv;
    const float x0s = x0 * x0, x1s = x1 * x1, x2s = x2 * x2, x3s = x3 * x3;
    // Row (y) start for this thread; row advances by 2 per iteration.
    const float ym0 = (float)(sub * 64 + (tid >> 7)) * inv - 1.0f;

    // Moment-shift accumulators: S=T0, Sy=ym0*T0+dy*T1, Syy=ym0^2*T0+2*ym0*dy*T1+dy^2*T2
    float T0 = 0.f, T1 = 0.f, T2 = 0.f, Sx = 0.f, Sxx = 0.f;

    #pragma unroll
    for (int bb = 0; bb < QPT / BATCH; ++bb) {
        float4 v[BATCH];
        #pragma unroll
        for (int j = 0; j < BATCH; ++j)
            v[j] = __ldg(&pbase[(size_t)(bb * BATCH + j) * THREADS]);

        #pragma unroll
        for (int j = 0; j < BATCH; ++j) {
            const float fi = (float)(bb * BATCH + j);       // compile-time const
            float rs = (v[j].x + v[j].y) + (v[j].z + v[j].w);
            T0 += rs;
            T1 = fmaf(rs, fi, T1);
            T2 = fmaf(rs, fi * fi, T2);
            Sx  = fmaf(v[j].x, x0,  fmaf(v[j].y, x1,  fmaf(v[j].z, x2,  fmaf(v[j].w, x3,  Sx))));
            Sxx = fmaf(v[j].x, x0s, fmaf(v[j].y, x1s, fmaf(v[j].z, x2s, fmaf(v[j].w, x3s, Sxx))));
        }
    }

    // Reconstruct y moments for this thread.
    float S   = T0;
    float Sy  = fmaf(ym0, T0, dy * T1);
    float Syy = fmaf(ym0 * ym0, T0, fmaf(2.0f * ym0 * dy, T1, dy * dy * T2));

    // Warp reduction of the 5 sums.
    #pragma unroll
    for (int off = 16; off > 0; off >>= 1) {
        S   += __shfl_xor_sync(0xFFFFFFFFu, S,   off);
        Sx  += __shfl_xor_sync(0xFFFFFFFFu, Sx,  off);
        Sxx += __shfl_xor_sync(0xFFFFFFFFu, Sxx, off);
        Sy  += __shfl_xor_sync(0xFFFFFFFFu, Sy,  off);
        Syy += __shfl_xor_sync(0xFFFFFFFFu, Syy, off);
    }

    __shared__ float sh[8][5];
    __shared__ bool  isLast;
    const int wid = tid >> 5, lid = tid & 31;
    if (lid == 0) {
        sh[wid][0] = S; sh[wid][1] = Sx; sh[wid][2] = Sxx;
        sh[wid][3] = Sy; sh[wid][4] = Syy;
    }
    __syncthreads();

    // Single-writer store of the 5 block partials, release-ordered.
    if (tid == 0) {
        #pragma unroll
        for (int c = 0; c < 5; ++c) {
            float acc = 0.f;
            #pragma unroll
            for (int w = 0; w < 8; ++w) acc += sh[w][c];
            g_part[c][bid] = acc;
        }
        __threadfence();
        unsigned int t = atomicInc(&g_ticket, NPART - 1);  // wraps to 0 on last
        isLast = (t == NPART - 1);
    }
    __syncthreads();

    if (!isLast) return;

    // ---- Last block finalizes (partials are L2-hot) ----
    __shared__ float red[THREADS];
    float contrib = 0.f;
    if (tid < NIMG) {
        float s[5];
        #pragma unroll
        for (int c = 0; c < 5; ++c) {
            const float4* p4 = (const float4*)&g_part[c][tid * BLOCKS_PER_IMG];
            float4 a = p4[0], bq = p4[1];
            s[c] = ((a.x + a.y) + (a.z + a.w)) + ((bq.x + bq.y) + (bq.z + bq.w));
        }
        float k    = s[0] + 1e-8f;
        float invk = 1.0f / k;
        float xc   = s[1] * invk;
        float yc   = s[3] * invk;
        float spdf = s[0] * invk;   // Σ pdf (≈1)
        // v = Σ pdf (m - c)^2 = M2/k - 2 c^2 + c^2 * Σpdf
        float vx = s[2] * invk - 2.0f * xc * xc + xc * xc * spdf;
        float vy = s[4] * invk - 2.0f * yc * yc + yc * yc * spdf;
        contrib = vx + vy;
    }
    red[tid] = contrib;
    __syncthreads();
    #pragma unroll
    for (int off = THREADS / 2; off > 0; off >>= 1) {
        if (tid < off) red[tid] += red[tid + off];
        __syncthreads();
    }
    if (tid == 0) out[0] = red[0] / (float)B_DIM;
}

extern "C" void kernel_launch(void* const* d_in, const int* in_sizes, int n_in,
                              void* d_out, int out_size) {
    const float* in = (const float*)d_in[0];
    float* out = (float*)d_out;
    fused_kernel<<<NPART, THREADS>>>(in, out);
}

// round 9
// speedup vs baseline: 1.1319x; 1.0010x over previous
#include <cuda_runtime.h>

// Problem constants: pred_softmax (16, 11, 1, 512, 512) fp32; use parts 0..9.
#define B_DIM   16
#define P_FULL  11
#define P_USE   10
#define HW      512
#define NIMG    (B_DIM * P_USE)            // 160
#define SLABS_PER_IMG 16                   // 32 rows per slab
#define NSLAB   (NIMG * SLABS_PER_IMG)     // 2560
#define GRID    592                        // 148 SMs x 4 CTAs: exactly one wave
#define THREADS 256
#define QPS     16                         // float4 quads per thread per slab
#define BATCH   8                          // loads in flight per thread

// SoA per-slab partials: [S, Sx, Sxx, Sy, Syy] x NSLAB.
__device__ __align__(16) float g_part[5][NSLAB];
// Work counter: exactly NSLAB+GRID increments per launch, wraps back to 0.
__device__ unsigned int g_work;
// Completion ticket: exactly NSLAB increments per launch, wraps back to 0.
__device__ unsigned int g_ticket;

__global__ __launch_bounds__(THREADS, 4) void fused_kernel(const float* __restrict__ in,
                                                           float* __restrict__ out) {
    const int tid = threadIdx.x;
    const int wid = tid >> 5, lid = tid & 31;
    const float inv = 2.0f / (float)HW;     // exact in fp32
    const float dy  = 2.0f * inv;           // row step per iteration (2 rows)

    // Per-thread x coordinates (column fixed: cq = tid & 127).
    const float x0 = (float)(4 * (tid & 127)) * inv - 1.0f;
    const float x1 = x0 + inv;
    const float x2 = x0 + 2.0f * inv;
    const float x3 = x0 + 3.0f * inv;
    const float x0s = x0 * x0, x1s = x1 * x1, x2s = x2 * x2, x3s = x3 * x3;

    __shared__ float sh[8][5];
    __shared__ int   s_slab;
    __shared__ bool  s_last;
    bool lastFlag = false;

    for (;;) {
        if (tid == 0) {
            unsigned int v = atomicInc(&g_work, NSLAB + GRID - 1);
            s_slab = (int)v;
        }
        __syncthreads();
        const int slab = s_slab;
        if (slab >= NSLAB) break;

        const int img = slab >> 4;          // 0..159
        const int sub = slab & 15;          // 0..15 (32-row slab)
        const int b = img / P_USE;
        const int p = img % P_USE;

        // Slab is contiguous: 32 rows x 128 quads = 4096 quads.
        const float4* __restrict__ pbase =
            (const float4*)(in + ((size_t)b * P_FULL + p) * (size_t)HW * HW)
            + (size_t)sub * 4096 + tid;

        // Row start for this thread; advances by 2 rows per iteration.
        const float ym0 = (float)(sub * 32 + (tid >> 7)) * inv - 1.0f;

        // Moment-shift accumulators.
        float T0 = 0.f, T1 = 0.f, T2 = 0.f, Sx = 0.f, Sxx = 0.f;

        #pragma unroll
        for (int bb = 0; bb < QPS / BATCH; ++bb) {
            float4 v[BATCH];
            #pragma unroll
            for (int j = 0; j < BATCH; ++j)
                v[j] = __ldg(&pbase[(size_t)(bb * BATCH + j) * THREADS]);

            #pragma unroll
            for (int j = 0; j < BATCH; ++j) {
                const float fi = (float)(bb * BATCH + j);   // compile-time const
                float rs = (v[j].x + v[j].y) + (v[j].z + v[j].w);
                T0 += rs;
                T1 = fmaf(rs, fi, T1);
                T2 = fmaf(rs, fi * fi, T2);
                Sx  = fmaf(v[j].x, x0,  fmaf(v[j].y, x1,  fmaf(v[j].z, x2,  fmaf(v[j].w, x3,  Sx))));
                Sxx = fmaf(v[j].x, x0s, fmaf(v[j].y, x1s, fmaf(v[j].z, x2s, fmaf(v[j].w, x3s, Sxx))));
            }
        }

        // Reconstruct y moments: ym_i = ym0 + dy*i.
        float S   = T0;
        float Sy  = fmaf(ym0, T0, dy * T1);
        float Syy = fmaf(ym0 * ym0, T0, fmaf(2.0f * ym0 * dy, T1, dy * dy * T2));

        // Warp reduction of the 5 sums.
        #pragma unroll
        for (int off = 16; off > 0; off >>= 1) {
            S   += __shfl_xor_sync(0xFFFFFFFFu, S,   off);
            Sx  += __shfl_xor_sync(0xFFFFFFFFu, Sx,  off);
            Sxx += __shfl_xor_sync(0xFFFFFFFFu, Sxx, off);
            Sy  += __shfl_xor_sync(0xFFFFFFFFu, Sy,  off);
            Syy += __shfl_xor_sync(0xFFFFFFFFu, Syy, off);
        }
        if (lid == 0) {
            sh[wid][0] = S; sh[wid][1] = Sx; sh[wid][2] = Sxx;
            sh[wid][3] = Sy; sh[wid][4] = Syy;
        }
        __syncthreads();

        // Single-writer store of the slab partials, release-ordered ticket.
        if (tid == 0) {
            #pragma unroll
            for (int c = 0; c < 5; ++c) {
                float acc = 0.f;
                #pragma unroll
                for (int w = 0; w < 8; ++w) acc += sh[w][c];
                g_part[c][slab] = acc;
            }
            __threadfence();
            unsigned int t = atomicInc(&g_ticket, NSLAB - 1);  // wraps to 0 on last
            if (t == NSLAB - 1) lastFlag = true;
        }
        // (The post-store __syncthreads at loop top doubles as the sh[] reuse guard.)
    }

    if (tid == 0) s_last = lastFlag;
    __syncthreads();
    if (!s_last) return;

    // ---- Last-completing block finalizes (partials are L2-hot) ----
    __shared__ float red[THREADS];
    float contrib = 0.f;
    if (tid < NIMG) {
        float s[5];
        #pragma unroll
        for (int c = 0; c < 5; ++c) {
            const float4* p4 = (const float4*)&g_part[c][tid * SLABS_PER_IMG];
            float4 a = p4[0], bq = p4[1], cc = p4[2], d = p4[3];
            s[c] = ((a.x + a.y) + (a.z + a.w)) + ((bq.x + bq.y) + (bq.z + bq.w))
                 + ((cc.x + cc.y) + (cc.z + cc.w)) + ((d.x + d.y) + (d.z + d.w));
        }
        float k    = s[0] + 1e-8f;
        float invk = 1.0f / k;
        float xc   = s[1] * invk;
        float yc   = s[3] * invk;
        float spdf = s[0] * invk;   // Σ pdf (≈1)
        // v = Σ pdf (m - c)^2 = M2/k - 2 c^2 + c^2 * Σpdf
        float vx = s[2] * invk - 2.0f * xc * xc + xc * xc * spdf;
        float vy = s[4] * invk - 2.0f * yc * yc + yc * yc * spdf;
        contrib = vx + vy;
    }
    red[tid] = contrib;
    __syncthreads();
    #pragma unroll
    for (int off = THREADS / 2; off > 0; off >>= 1) {
        if (tid < off) red[tid] += red[tid + off];
        __syncthreads();
    }
    if (tid == 0) out[0] = red[0] / (float)B_DIM;
}

extern "C" void kernel_launch(void* const* d_in, const int* in_sizes, int n_in,
                              void* d_out, int out_size) {
    const float* in = (const float*)d_in[0];
    float* out = (float*)d_out;
    fused_kernel<<<GRID, THREADS>>>(in, out);
}